// round 7
// baseline (speedup 1.0000x reference)
#include <cuda_runtime.h>
#include <cuda_fp16.h>
#include <cstdint>
#include <math.h>

#define NN 8192
#define FIN 256
#define HD_TOT 256

// Scratch (allocation-free rule: __device__ globals)
__device__ float  g_h[NN * HD_TOT];                     // fp32 h = x @ W (for K2)
__device__ __align__(16) __half g_hh[NN * HD_TOT];      // fp16 h (MMA B operand)
__device__ float4 g_spack[NN * 4];                      // {s, e^s, e^{0.2s}, _}
__device__ __half g_dE1[4 * NN];                        // head-major: e^{d_j}
__device__ __half g_dE2[4 * NN];                        // head-major: e^{0.2 d_j}

// ---------------------------------------------------------------------------
// K1: g_h / g_hh = x @ W   (8192x256 @ 256x256), 64x64 tiles, 4x4 micro
// ---------------------------------------------------------------------------
__global__ __launch_bounds__(256) void k1_linear(const float* __restrict__ x,
                                                 const float* __restrict__ W) {
    __shared__ float as[32][68];
    __shared__ float bs[32][64];
    const int rbase = blockIdx.x * 64;
    const int cbase = blockIdx.y * 64;
    const int tid = threadIdx.x;
    const int tm = tid >> 4, tn = tid & 15;
    float acc[4][4];
#pragma unroll
    for (int u = 0; u < 4; u++)
#pragma unroll
        for (int v = 0; v < 4; v++) acc[u][v] = 0.f;

    for (int k0 = 0; k0 < FIN; k0 += 32) {
        __syncthreads();
#pragma unroll
        for (int q = 0; q < 2; q++) {
            int f = tid + 256 * q;
            int row = f >> 3, c4 = (f & 7) * 4;
            float4 v = *(const float4*)&x[(rbase + row) * FIN + k0 + c4];
            as[c4 + 0][row] = v.x;
            as[c4 + 1][row] = v.y;
            as[c4 + 2][row] = v.z;
            as[c4 + 3][row] = v.w;
        }
#pragma unroll
        for (int q = 0; q < 2; q++) {
            int f = tid + 256 * q;
            int row = f >> 4, c4 = (f & 15) * 4;
            *(float4*)&bs[row][c4] = *(const float4*)&W[(k0 + row) * HD_TOT + cbase + c4];
        }
        __syncthreads();
#pragma unroll
        for (int k = 0; k < 32; k++) {
            float a[4], b[4];
            *(float4*)a = *(float4*)&as[k][tm * 4];
            *(float4*)b = *(float4*)&bs[k][tn * 4];
#pragma unroll
            for (int u = 0; u < 4; u++)
#pragma unroll
                for (int v = 0; v < 4; v++) acc[u][v] = fmaf(a[u], b[v], acc[u][v]);
        }
    }
#pragma unroll
    for (int u = 0; u < 4; u++) {
        size_t off = (size_t)(rbase + tm * 4 + u) * HD_TOT + cbase + tn * 4;
        *(float4*)&g_h[off] = make_float4(acc[u][0], acc[u][1], acc[u][2], acc[u][3]);
        __half2* hp = (__half2*)&g_hh[off];
        hp[0] = __floats2half2_rn(acc[u][0], acc[u][1]);
        hp[1] = __floats2half2_rn(acc[u][2], acc[u][3]);
    }
}

// ---------------------------------------------------------------------------
// K2: per-node per-head scores s,d; exp factorizations (fp32 s-side, fp16 d-side)
// ---------------------------------------------------------------------------
__global__ __launch_bounds__(256) void k2_scores(const float* __restrict__ a_src,
                                                 const float* __restrict__ a_dst) {
    const int n = blockIdx.x * 8 + (threadIdx.x >> 5);
    const int lane = threadIdx.x & 31;
    const float* hrow = g_h + (size_t)n * HD_TOT;
#pragma unroll
    for (int h = 0; h < 4; h++) {
        float h0 = hrow[h * 64 + lane];
        float h1 = hrow[h * 64 + 32 + lane];
        float sv = h0 * a_src[h * 64 + lane] + h1 * a_src[h * 64 + 32 + lane];
        float dv = h0 * a_dst[h * 64 + lane] + h1 * a_dst[h * 64 + 32 + lane];
#pragma unroll
        for (int off = 16; off > 0; off >>= 1) {
            sv += __shfl_xor_sync(0xffffffffu, sv, off);
            dv += __shfl_xor_sync(0xffffffffu, dv, off);
        }
        if (lane == 0) {
            g_spack[n * 4 + h] = make_float4(sv, expf(sv), expf(0.2f * sv), 0.f);
            g_dE1[h * NN + n] = __float2half_rn(expf(dv));
            g_dE2[h * NN + n] = __float2half_rn(expf(0.2f * dv));
        }
    }
}

// ---------------------------------------------------------------------------
// PTX helpers
// ---------------------------------------------------------------------------
__device__ __forceinline__ void mma16816(float* c, const unsigned* a,
                                         unsigned b0, unsigned b1) {
    asm volatile("mma.sync.aligned.m16n8k16.row.col.f32.f16.f16.f32 "
                 "{%0,%1,%2,%3}, {%4,%5,%6,%7}, {%8,%9}, {%0,%1,%2,%3};"
                 : "+f"(c[0]), "+f"(c[1]), "+f"(c[2]), "+f"(c[3])
                 : "r"(a[0]), "r"(a[1]), "r"(a[2]), "r"(a[3]), "r"(b0), "r"(b1));
}

__device__ __forceinline__ void ldsm_x4_trans(unsigned& r0, unsigned& r1,
                                              unsigned& r2, unsigned& r3,
                                              unsigned addr) {
    asm volatile("ldmatrix.sync.aligned.m8n8.x4.trans.shared.b16 {%0,%1,%2,%3}, [%4];"
                 : "=r"(r0), "=r"(r1), "=r"(r2), "=r"(r3) : "r"(addr));
}

__device__ __forceinline__ void ldsm_x2_trans(unsigned& r0, unsigned& r1,
                                              unsigned addr) {
    asm volatile("ldmatrix.sync.aligned.m8n8.x2.trans.shared.b16 {%0,%1}, [%2];"
                 : "=r"(r0), "=r"(r1) : "r"(addr));
}

// w(half2) = max(A1*E1, A2*E2) & adj-mask   (exp(lrelu) == max of the two exps)
__device__ __forceinline__ unsigned gat_w2(__half2 A1, __half2 A2,
                                           __half2 E1, __half2 E2, int2 av) {
    __half2 w = __hmax2(__hmul2(A1, E1), __hmul2(A2, E2));
    unsigned m = (unsigned)av.x * 0x0000FFFFu + (unsigned)av.y * 0xFFFF0000u;
    return (*(unsigned*)&w) & m;
}

// ---------------------------------------------------------------------------
// K3: tensor-core masked-softmax aggregation.
// 512 threads: 16 warps = 4 row-groups x 4 heads. Block = 64 rows, all heads.
// A fragments built in registers (half2 max-trick). Ones-column 9th tile -> Z.
// ---------------------------------------------------------------------------
#define HS_PITCH 264   // halfs per row: 256 data + 8 ones-tile

__global__ __launch_bounds__(512, 1) void k3_mma(const int* __restrict__ adj,
                                                 const float* __restrict__ bias,
                                                 float* __restrict__ out) {
    __shared__ __align__(16) __half hs[32 * HS_PITCH];   // B tile [k=32][256+8]
    __shared__ __align__(4)  __half es1[4][36];          // e^{d} per head, this chunk
    __shared__ __align__(4)  __half es2[4][36];          // e^{0.2 d}

    const int tid = threadIdx.x;
    const int lane = tid & 31, warp = tid >> 5;
    const int wr = warp & 3;            // row group
    const int hh = warp >> 2;           // head 0..3
    const int g = lane >> 2, t = lane & 3;
    const int ibase = blockIdx.x * 64;
    const int row0 = ibase + wr * 16 + g;   // rows: row0, row0+8

    // hoisted src-side factors (broadcast half2)
    float4 s0 = g_spack[row0 * 4 + hh];
    float4 s1 = g_spack[(row0 + 8) * 4 + hh];
    const __half2 A1r0 = __float2half2_rn(s0.y), A2r0 = __float2half2_rn(s0.z);
    const __half2 A1r1 = __float2half2_rn(s1.y), A2r1 = __float2half2_rn(s1.z);

    // ones tile (cols 256..263): col 256 = 1, rest 0
    if (tid < 32) {
        hs[tid * HS_PITCH + 256] = __float2half(1.0f);
#pragma unroll
        for (int c = 1; c < 8; c++) hs[tid * HS_PITCH + 256 + c] = __float2half(0.0f);
    }

    float acc[9][4];
#pragma unroll
    for (int nt = 0; nt < 9; nt++)
#pragma unroll
        for (int r = 0; r < 4; r++) acc[nt][r] = 0.f;

    const unsigned hs_u = (unsigned)__cvta_generic_to_shared(hs);
    const int* a0p = adj + (size_t)row0 * NN;
    const int* a1p = adj + (size_t)(row0 + 8) * NN;

    for (int jb = 0; jb < NN; jb += 32) {
        __syncthreads();
        // stage B: h fp16 rows jb..jb+31 (1024 int4 over 512 threads)
#pragma unroll
        for (int q = 0; q < 2; q++) {
            int f = tid + 512 * q;
            int r = f >> 5, c8 = (f & 31) * 8;
            *(int4*)&hs[r * HS_PITCH + c8] =
                *(const int4*)&g_hh[(size_t)(jb + r) * HD_TOT + c8];
        }
        // stage dst-side exp factors for this chunk (4 heads x 32 j)
        if (tid < 128) {
            es1[tid >> 5][tid & 31] = g_dE1[(tid >> 5) * NN + jb + (tid & 31)];
        } else if (tid < 256) {
            int u = tid - 128;
            es2[u >> 5][u & 31] = g_dE2[(u >> 5) * NN + jb + (u & 31)];
        }
        __syncthreads();

        // batched adj loads (8 x LDG.64)
        int2 av[2][2], bv[2][2];
#pragma unroll
        for (int ks = 0; ks < 2; ks++)
#pragma unroll
            for (int jp = 0; jp < 2; jp++) {
                int j0 = jb + ks * 16 + jp * 8 + t * 2;
                av[ks][jp] = *(const int2*)(a0p + j0);
                bv[ks][jp] = *(const int2*)(a1p + j0);
            }

        // build A fragments (half2 max-trick) + MMA
        unsigned afr[2][4];
#pragma unroll
        for (int ks = 0; ks < 2; ks++) {
#pragma unroll
            for (int jp = 0; jp < 2; jp++) {
                int j0 = ks * 16 + jp * 8 + t * 2;
                __half2 E1 = *(const __half2*)&es1[hh][j0];
                __half2 E2 = *(const __half2*)&es2[hh][j0];
                afr[ks][jp * 2 + 0] = gat_w2(A1r0, A2r0, E1, E2, av[ks][jp]);
                afr[ks][jp * 2 + 1] = gat_w2(A1r1, A2r1, E1, E2, bv[ks][jp]);
            }
        }

#pragma unroll
        for (int ks = 0; ks < 2; ks++) {
            const unsigned rowaddr = hs_u + ((ks * 16 + (lane & 15)) * HS_PITCH) * 2;
            const int cb = hh * 64;
#pragma unroll
            for (int ntp = 0; ntp < 4; ntp++) {
                unsigned b0, b1, b2, b3;
                unsigned baddr = rowaddr + (cb + ntp * 16 + (lane >> 4) * 8) * 2;
                ldsm_x4_trans(b0, b1, b2, b3, baddr);
                mma16816(acc[ntp * 2 + 0], afr[ks], b0, b1);
                mma16816(acc[ntp * 2 + 1], afr[ks], b2, b3);
            }
            // ones tile -> Z
            unsigned o0, o1;
            ldsm_x2_trans(o0, o1, rowaddr + 256 * 2);
            mma16816(acc[8], afr[ks], o0, o1);
        }
    }

    // epilogue: normalize by Z, add bias
    float Z0 = __shfl_sync(0xffffffffu, acc[8][0], lane & 0x1c);
    float Z1 = __shfl_sync(0xffffffffu, acc[8][2], lane & 0x1c);
    float i0 = 1.f / Z0;
    float i1 = 1.f / Z1;
#pragma unroll
    for (int nt = 0; nt < 8; nt++) {
        int col = hh * 64 + nt * 8 + t * 2;
        float b0v = bias[col], b1v = bias[col + 1];
        float2 v0 = make_float2(acc[nt][0] * i0 + b0v, acc[nt][1] * i0 + b1v);
        float2 v1 = make_float2(acc[nt][2] * i1 + b0v, acc[nt][3] * i1 + b1v);
        *(float2*)&out[(size_t)row0 * HD_TOT + col] = v0;
        *(float2*)&out[(size_t)(row0 + 8) * HD_TOT + col] = v1;
    }
}

// ---------------------------------------------------------------------------
extern "C" void kernel_launch(void* const* d_in, const int* in_sizes, int n_in,
                              void* d_out, int out_size) {
    const float* x     = (const float*)d_in[0];
    const int*   adj   = (const int*)d_in[1];
    const float* W     = (const float*)d_in[2];
    const float* a_src = (const float*)d_in[3];
    const float* a_dst = (const float*)d_in[4];
    const float* bias  = (const float*)d_in[5];
    float* out = (float*)d_out;

    (void)in_sizes; (void)n_in; (void)out_size;

    k1_linear<<<dim3(NN / 64, HD_TOT / 64), 256>>>(x, W);
    k2_scores<<<NN / 8, 256>>>(a_src, a_dst);
    k3_mma<<<NN / 64, 512>>>(adj, bias, out);
}

// round 8
// speedup vs baseline: 1.6133x; 1.6133x over previous
#include <cuda_runtime.h>
#include <cuda_fp16.h>
#include <cstdint>
#include <math.h>

#define NN 8192
#define FIN 256
#define HD_TOT 256

// Scratch (allocation-free rule: __device__ globals)
__device__ float  g_h[NN * HD_TOT];                     // fp32 h = x @ W (for K2)
__device__ __align__(16) __half g_hh[NN * HD_TOT];      // fp16 h (MMA B operand)
__device__ float4 g_spack[NN * 4];                      // {s, e^s, e^{0.2s}, _}
__device__ __half g_dE1[4 * NN];                        // head-major: e^{d_j}
__device__ __half g_dE2[4 * NN];                        // head-major: e^{0.2 d_j}
__device__ __align__(16) unsigned g_adjbit[NN * (NN / 32)];  // 8 MB bitmask

// ---------------------------------------------------------------------------
// K0: pack adj (256 MB int32 0/1) into bitmask (8 MB). bit b of word jw for
// row i  <=>  adj[i][jw*32+b]. One warp packs 128 consecutive words.
// ---------------------------------------------------------------------------
__global__ __launch_bounds__(256) void k0_pack(const int* __restrict__ adj) {
    const int gw = (blockIdx.x * blockDim.x + threadIdx.x) >> 5;  // global warp
    const int lane = threadIdx.x & 31;
    const int* base = adj + (size_t)gw * 128 * 32;
    unsigned* outw = g_adjbit + (size_t)gw * 128;
    for (int k = 0; k < 128; k += 4) {
        int v0 = base[(k + 0) * 32 + lane];
        int v1 = base[(k + 1) * 32 + lane];
        int v2 = base[(k + 2) * 32 + lane];
        int v3 = base[(k + 3) * 32 + lane];
        unsigned b0 = __ballot_sync(0xffffffffu, v0 != 0);
        unsigned b1 = __ballot_sync(0xffffffffu, v1 != 0);
        unsigned b2 = __ballot_sync(0xffffffffu, v2 != 0);
        unsigned b3 = __ballot_sync(0xffffffffu, v3 != 0);
        if (lane == 0) *(uint4*)&outw[k] = make_uint4(b0, b1, b2, b3);
    }
}

// ---------------------------------------------------------------------------
// K1: g_h / g_hh = x @ W   (8192x256 @ 256x256), 64x64 tiles, 4x4 micro
// ---------------------------------------------------------------------------
__global__ __launch_bounds__(256) void k1_linear(const float* __restrict__ x,
                                                 const float* __restrict__ W) {
    __shared__ float as[32][68];
    __shared__ float bs[32][64];
    const int rbase = blockIdx.x * 64;
    const int cbase = blockIdx.y * 64;
    const int tid = threadIdx.x;
    const int tm = tid >> 4, tn = tid & 15;
    float acc[4][4];
#pragma unroll
    for (int u = 0; u < 4; u++)
#pragma unroll
        for (int v = 0; v < 4; v++) acc[u][v] = 0.f;

    for (int k0 = 0; k0 < FIN; k0 += 32) {
        __syncthreads();
#pragma unroll
        for (int q = 0; q < 2; q++) {
            int f = tid + 256 * q;
            int row = f >> 3, c4 = (f & 7) * 4;
            float4 v = *(const float4*)&x[(rbase + row) * FIN + k0 + c4];
            as[c4 + 0][row] = v.x;
            as[c4 + 1][row] = v.y;
            as[c4 + 2][row] = v.z;
            as[c4 + 3][row] = v.w;
        }
#pragma unroll
        for (int q = 0; q < 2; q++) {
            int f = tid + 256 * q;
            int row = f >> 4, c4 = (f & 15) * 4;
            *(float4*)&bs[row][c4] = *(const float4*)&W[(k0 + row) * HD_TOT + cbase + c4];
        }
        __syncthreads();
#pragma unroll
        for (int k = 0; k < 32; k++) {
            float a[4], b[4];
            *(float4*)a = *(float4*)&as[k][tm * 4];
            *(float4*)b = *(float4*)&bs[k][tn * 4];
#pragma unroll
            for (int u = 0; u < 4; u++)
#pragma unroll
                for (int v = 0; v < 4; v++) acc[u][v] = fmaf(a[u], b[v], acc[u][v]);
        }
    }
#pragma unroll
    for (int u = 0; u < 4; u++) {
        size_t off = (size_t)(rbase + tm * 4 + u) * HD_TOT + cbase + tn * 4;
        *(float4*)&g_h[off] = make_float4(acc[u][0], acc[u][1], acc[u][2], acc[u][3]);
        __half2* hp = (__half2*)&g_hh[off];
        hp[0] = __floats2half2_rn(acc[u][0], acc[u][1]);
        hp[1] = __floats2half2_rn(acc[u][2], acc[u][3]);
    }
}

// ---------------------------------------------------------------------------
// K2: per-node per-head scores s,d; exp factorizations
// ---------------------------------------------------------------------------
__global__ __launch_bounds__(256) void k2_scores(const float* __restrict__ a_src,
                                                 const float* __restrict__ a_dst) {
    const int n = blockIdx.x * 8 + (threadIdx.x >> 5);
    const int lane = threadIdx.x & 31;
    const float* hrow = g_h + (size_t)n * HD_TOT;
#pragma unroll
    for (int h = 0; h < 4; h++) {
        float h0 = hrow[h * 64 + lane];
        float h1 = hrow[h * 64 + 32 + lane];
        float sv = h0 * a_src[h * 64 + lane] + h1 * a_src[h * 64 + 32 + lane];
        float dv = h0 * a_dst[h * 64 + lane] + h1 * a_dst[h * 64 + 32 + lane];
#pragma unroll
        for (int off = 16; off > 0; off >>= 1) {
            sv += __shfl_xor_sync(0xffffffffu, sv, off);
            dv += __shfl_xor_sync(0xffffffffu, dv, off);
        }
        if (lane == 0) {
            g_spack[n * 4 + h] = make_float4(sv, expf(sv), expf(0.2f * sv), 0.f);
            g_dE1[h * NN + n] = __float2half_rn(expf(dv));
            g_dE2[h * NN + n] = __float2half_rn(expf(0.2f * dv));
        }
    }
}

// ---------------------------------------------------------------------------
// PTX helpers
// ---------------------------------------------------------------------------
__device__ __forceinline__ void mma16816(float* c, const unsigned* a,
                                         unsigned b0, unsigned b1) {
    asm volatile("mma.sync.aligned.m16n8k16.row.col.f32.f16.f16.f32 "
                 "{%0,%1,%2,%3}, {%4,%5,%6,%7}, {%8,%9}, {%0,%1,%2,%3};"
                 : "+f"(c[0]), "+f"(c[1]), "+f"(c[2]), "+f"(c[3])
                 : "r"(a[0]), "r"(a[1]), "r"(a[2]), "r"(a[3]), "r"(b0), "r"(b1));
}

__device__ __forceinline__ void ldsm_x4_trans(unsigned& r0, unsigned& r1,
                                              unsigned& r2, unsigned& r3,
                                              unsigned addr) {
    asm volatile("ldmatrix.sync.aligned.m8n8.x4.trans.shared.b16 {%0,%1,%2,%3}, [%4];"
                 : "=r"(r0), "=r"(r1), "=r"(r2), "=r"(r3) : "r"(addr));
}

__device__ __forceinline__ void ldsm_x2_trans(unsigned& r0, unsigned& r1,
                                              unsigned addr) {
    asm volatile("ldmatrix.sync.aligned.m8n8.x2.trans.shared.b16 {%0,%1}, [%2];"
                 : "=r"(r0), "=r"(r1) : "r"(addr));
}

__device__ __forceinline__ void cp_async16(unsigned smem_addr, const void* gptr) {
    asm volatile("cp.async.cg.shared.global [%0], [%1], 16;"
                 :: "r"(smem_addr), "l"(gptr));
}
__device__ __forceinline__ void cp_commit() {
    asm volatile("cp.async.commit_group;");
}
__device__ __forceinline__ void cp_wait1() {
    asm volatile("cp.async.wait_group 1;" ::: "memory");
}
__device__ __forceinline__ void cp_wait0() {
    asm volatile("cp.async.wait_group 0;" ::: "memory");
}

// w(half2) = max(A1*E1, A2*E2) masked by 2 adj bits (j0, j0+1) of word w.
__device__ __forceinline__ unsigned gat_w2(__half2 A1, __half2 A2,
                                           __half2 E1, __half2 E2,
                                           unsigned w, int j0) {
    __half2 p = __hmax2(__hmul2(A1, E1), __hmul2(A2, E2));
    unsigned b = (w >> j0) & 3u;
    unsigned m = (b & 1u) * 0x0000FFFFu + (b >> 1) * 0xFFFF0000u;
    return (*(unsigned*)&p) & m;
}

// ---------------------------------------------------------------------------
// K3: tensor-core masked-softmax aggregation, bitmask adj + cp.async pipeline.
// 512 threads: 16 warps = 4 row-groups x 4 heads. Block = 64 rows, all heads.
// ---------------------------------------------------------------------------
#define HS_PITCH 264                         // halfs: 256 data + 8 ones-tile
#define HS_BUF   (32 * HS_PITCH)             // halfs per buffer
#define HS_BUFB  (HS_BUF * 2)                // bytes per buffer

__global__ __launch_bounds__(512, 1) void k3_mma(const float* __restrict__ bias,
                                                 float* __restrict__ out) {
    __shared__ __align__(16) __half hs[2 * HS_BUF];

    const int tid = threadIdx.x;
    const int lane = tid & 31, warp = tid >> 5;
    const int wr = warp & 3;
    const int hh = warp >> 2;
    const int g = lane >> 2, t = lane & 3;
    const int ibase = blockIdx.x * 64;
    const int row0 = ibase + wr * 16 + g;    // rows: row0, row0+8

    float4 s0 = g_spack[row0 * 4 + hh];
    float4 s1 = g_spack[(row0 + 8) * 4 + hh];
    const __half2 A1r0 = __float2half2_rn(s0.y), A2r0 = __float2half2_rn(s0.z);
    const __half2 A1r1 = __float2half2_rn(s1.y), A2r1 = __float2half2_rn(s1.z);

    // ones tiles (cols 256..263) in both buffers, written once
    if (tid < 64) {
        __half* p = &hs[(tid >> 5) * HS_BUF + (tid & 31) * HS_PITCH + 256];
        p[0] = __float2half(1.0f);
#pragma unroll
        for (int c = 1; c < 8; c++) p[c] = __float2half(0.0f);
    }

    float acc[9][4];
#pragma unroll
    for (int nt = 0; nt < 9; nt++)
#pragma unroll
        for (int r = 0; r < 4; r++) acc[nt][r] = 0.f;

    const unsigned hs_u = (unsigned)__cvta_generic_to_shared(hs);
    const int r_st = tid >> 5, c8_st = (tid & 31) * 8;        // staging coords (q=0)
    const int r_st2 = r_st + 16;                               // q=1

    // prologue: stage chunk 0 into buffer 0
    cp_async16(hs_u + (r_st * HS_PITCH + c8_st) * 2,
               &g_hh[(size_t)r_st * HD_TOT + c8_st]);
    cp_async16(hs_u + (r_st2 * HS_PITCH + c8_st) * 2,
               &g_hh[(size_t)r_st2 * HD_TOT + c8_st]);
    cp_commit();

    const unsigned* bm0 = g_adjbit + (size_t)row0 * (NN / 32);
    const unsigned* bm1 = g_adjbit + (size_t)(row0 + 8) * (NN / 32);
    const __half* e1p = g_dE1 + hh * NN;
    const __half* e2p = g_dE2 + hh * NN;

    int buf = 0;
    for (int it = 0; it < NN / 32; it++) {
        const int jb = it * 32;
        if (it + 1 < NN / 32) {
            const unsigned dstb = hs_u + (buf ^ 1) * HS_BUFB;
            cp_async16(dstb + (r_st * HS_PITCH + c8_st) * 2,
                       &g_hh[(size_t)(jb + 32 + r_st) * HD_TOT + c8_st]);
            cp_async16(dstb + (r_st2 * HS_PITCH + c8_st) * 2,
                       &g_hh[(size_t)(jb + 32 + r_st2) * HD_TOT + c8_st]);
            cp_commit();
            cp_wait1();
        } else {
            cp_wait0();
        }
        __syncthreads();

        // adj bits (L2-resident bitmask) + E factors (L1-hot)
        const unsigned w0 = bm0[it];
        const unsigned w1 = bm1[it];

        unsigned afr[2][4];
#pragma unroll
        for (int ks = 0; ks < 2; ks++) {
#pragma unroll
            for (int jp = 0; jp < 2; jp++) {
                const int j0 = ks * 16 + jp * 8 + t * 2;
                const __half2 E1 = *(const __half2*)&e1p[jb + j0];
                const __half2 E2 = *(const __half2*)&e2p[jb + j0];
                afr[ks][jp * 2 + 0] = gat_w2(A1r0, A2r0, E1, E2, w0, j0);
                afr[ks][jp * 2 + 1] = gat_w2(A1r1, A2r1, E1, E2, w1, j0);
            }
        }

        const unsigned hb = hs_u + buf * HS_BUFB;
#pragma unroll
        for (int ks = 0; ks < 2; ks++) {
            const unsigned rowaddr = hb + ((ks * 16 + (lane & 15)) * HS_PITCH) * 2;
            const int cb = hh * 64;
#pragma unroll
            for (int ntp = 0; ntp < 4; ntp++) {
                unsigned b0, b1, b2, b3;
                unsigned baddr = rowaddr + (cb + ntp * 16 + (lane >> 4) * 8) * 2;
                ldsm_x4_trans(b0, b1, b2, b3, baddr);
                mma16816(acc[ntp * 2 + 0], afr[ks], b0, b1);
                mma16816(acc[ntp * 2 + 1], afr[ks], b2, b3);
            }
            unsigned o0, o1;
            ldsm_x2_trans(o0, o1, rowaddr + 256 * 2);
            mma16816(acc[8], afr[ks], o0, o1);
        }
        __syncthreads();
        buf ^= 1;
    }

    // epilogue: normalize by Z, add bias
    float Z0 = __shfl_sync(0xffffffffu, acc[8][0], lane & 0x1c);
    float Z1 = __shfl_sync(0xffffffffu, acc[8][2], lane & 0x1c);
    float i0 = 1.f / Z0;
    float i1 = 1.f / Z1;
#pragma unroll
    for (int nt = 0; nt < 8; nt++) {
        int col = hh * 64 + nt * 8 + t * 2;
        float b0v = bias[col], b1v = bias[col + 1];
        float2 v0 = make_float2(acc[nt][0] * i0 + b0v, acc[nt][1] * i0 + b1v);
        float2 v1 = make_float2(acc[nt][2] * i1 + b0v, acc[nt][3] * i1 + b1v);
        *(float2*)&out[(size_t)row0 * HD_TOT + col] = v0;
        *(float2*)&out[(size_t)(row0 + 8) * HD_TOT + col] = v1;
    }
}

// ---------------------------------------------------------------------------
extern "C" void kernel_launch(void* const* d_in, const int* in_sizes, int n_in,
                              void* d_out, int out_size) {
    const float* x     = (const float*)d_in[0];
    const int*   adj   = (const int*)d_in[1];
    const float* W     = (const float*)d_in[2];
    const float* a_src = (const float*)d_in[3];
    const float* a_dst = (const float*)d_in[4];
    const float* bias  = (const float*)d_in[5];
    float* out = (float*)d_out;

    (void)in_sizes; (void)n_in; (void)out_size;

    k0_pack<<<NN * (NN / 32) / (128 * 8), 256>>>(adj);
    k1_linear<<<dim3(NN / 64, HD_TOT / 64), 256>>>(x, W);
    k2_scores<<<NN / 8, 256>>>(a_src, a_dst);
    k3_mma<<<NN / 64, 512>>>(bias, out);
}